// round 14
// baseline (speedup 1.0000x reference)
#include <cuda_runtime.h>
#include <cuda_fp16.h>
#include <cstdint>

#define NN 50000
#define EE 800000

typedef unsigned long long ull;
typedef unsigned int u32;

__device__ __forceinline__ u32 saddr(const void* p) {
    return (u32)__cvta_generic_to_shared(p);
}
__device__ __forceinline__ void ldsm_x4(u32 &a0, u32 &a1, u32 &a2, u32 &a3, u32 addr) {
    asm volatile("ldmatrix.sync.aligned.m8n8.x4.shared.b16 {%0,%1,%2,%3}, [%4];"
                 : "=r"(a0), "=r"(a1), "=r"(a2), "=r"(a3) : "r"(addr));
}
__device__ __forceinline__ void ldsm_x2t(u32 &b0, u32 &b1, u32 addr) {
    asm volatile("ldmatrix.sync.aligned.m8n8.x2.trans.shared.b16 {%0,%1}, [%2];"
                 : "=r"(b0), "=r"(b1) : "r"(addr));
}
__device__ __forceinline__ void mma16816(float &c0, float &c1, float &c2, float &c3,
                                         u32 a0, u32 a1, u32 a2, u32 a3,
                                         u32 b0, u32 b1) {
    asm volatile(
        "mma.sync.aligned.m16n8k16.row.col.f32.f16.f16.f32 "
        "{%0,%1,%2,%3}, {%4,%5,%6,%7}, {%8,%9}, {%0,%1,%2,%3};"
        : "+f"(c0), "+f"(c1), "+f"(c2), "+f"(c3)
        : "r"(a0), "r"(a1), "r"(a2), "r"(a3), "r"(b0), "r"(b1));
}

// ---------------- scratch ----------------
__device__ float g_dinv[NN];
__device__ int   g_indeg[NN];
__device__ int   g_cur[NN];
__device__ int   g_off[NN + 1];
__device__ int   g_adj[EE];
__device__ int   g_bsum[64];

__device__ __half g_y0h[NN * 64];
__device__ __half g_axh[NN * 64];
__device__ __half g_raw1h[NN * 128];
__device__ __half g_y1h[NN * 128];
__device__ __half g_agg1h[NN * 128];
__device__ __half g_raw2h[NN * 256];
__device__ __half g_y3h[NN * 64];
__device__ __half g_muh[NN * 32];

__device__ float g_ssum[512];
__device__ float g_ssq[512];

// ---------------- setup ----------------
__global__ void k_zero() {
    int i = blockIdx.x * blockDim.x + threadIdx.x;
    if (i < NN) { g_indeg[i] = 0; g_cur[i] = 0; }
    if (i < 512) { g_ssum[i] = 0.f; g_ssq[i] = 0.f; }
}

__global__ void k_indeg(const int* __restrict__ dst) {
    int e = blockIdx.x * blockDim.x + threadIdx.x;
    if (e < EE) atomicAdd(&g_indeg[dst[e]], 1);
}

__global__ void k_dinv_y0(const float* __restrict__ x) {
    int idx = blockIdx.x * blockDim.x + threadIdx.x;
    if (idx < NN * 16) {
        int row = idx >> 4;
        float d = rsqrtf((float)(g_indeg[row] + 1));
        if ((idx & 15) == 0) g_dinv[row] = d;
        float4 v = ((const float4*)x)[idx];
        __half2 h0 = __floats2half2_rn(v.x * d, v.y * d);
        __half2 h1 = __floats2half2_rn(v.z * d, v.w * d);
        ((uint2*)g_y0h)[idx] = make_uint2(*(unsigned*)&h0, *(unsigned*)&h1);
    }
}

// ---------------- CSR build ----------------
__global__ void k_scan1() {
    int i = blockIdx.x * 1024 + threadIdx.x;
    int v = (i < NN) ? g_indeg[i] : 0;
    int lane = threadIdx.x & 31, wid = threadIdx.x >> 5;
    int s = v;
    #pragma unroll
    for (int o = 1; o < 32; o <<= 1) {
        int t = __shfl_up_sync(~0u, s, o);
        if (lane >= o) s += t;
    }
    __shared__ int wsum[32];
    if (lane == 31) wsum[wid] = s;
    __syncthreads();
    if (wid == 0) {
        int ws = wsum[lane];
        #pragma unroll
        for (int o = 1; o < 32; o <<= 1) {
            int t = __shfl_up_sync(~0u, ws, o);
            if (lane >= o) ws += t;
        }
        wsum[lane] = ws;
    }
    __syncthreads();
    int incl = s + (wid > 0 ? wsum[wid - 1] : 0);
    if (i < NN) g_off[i + 1] = incl;
    if (threadIdx.x == 1023) g_bsum[blockIdx.x] = incl;
}

__global__ void k_scan3() {
    __shared__ int base;
    if (threadIdx.x == 0) {
        int acc = 0;
        for (int b = 0; b < blockIdx.x; b++) acc += g_bsum[b];
        base = acc;
    }
    __syncthreads();
    int i = blockIdx.x * 1024 + threadIdx.x;
    if (i < NN) g_off[i + 1] += base;
    if (i == 0) g_off[0] = 0;
}

__global__ void k_scatter(const int* __restrict__ src, const int* __restrict__ dst) {
    int e = blockIdx.x * blockDim.x + threadIdx.x;
    if (e < EE) {
        int d = dst[e];
        int p = g_off[d] + atomicAdd(&g_cur[d], 1);
        g_adj[p] = src[e];
    }
}

// ---------------- aggregations ----------------
__global__ void k_agg1h(const __half* __restrict__ y, __half* __restrict__ out) {
    int gw = (blockIdx.x * blockDim.x + threadIdx.x) >> 5;
    if (gw >= NN) return;
    int lane = threadIdx.x & 31;
    int beg = g_off[gw], end = g_off[gw + 1];
    float2 acc = __half22float2(*(const __half2*)(y + gw * 64 + lane * 2));
    for (int j = beg; j < end; j++) {
        int s = g_adj[j];
        float2 v = __half22float2(__ldg((const __half2*)(y + s * 64 + lane * 2)));
        acc.x += v.x; acc.y += v.y;
    }
    float d = g_dinv[gw];
    *(__half2*)(out + gw * 64 + lane * 2) = __floats2half2_rn(acc.x * d, acc.y * d);
}

// layer-2 aggregation: 2 warps per node, each warp covers 64 of 128 columns.
// Per-column edge-summation order unchanged -> bitwise-identical outputs.
__global__ void k_agg2h(const __half* __restrict__ y, __half* __restrict__ out) {
    int gw = (blockIdx.x * blockDim.x + threadIdx.x) >> 5;
    if (gw >= NN * 2) return;
    int node = gw >> 1, half = gw & 1;
    int lane = threadIdx.x & 31;
    int colb = half * 64 + lane * 2;
    int beg = g_off[node], end = g_off[node + 1];
    float2 acc = __half22float2(*(const __half2*)(y + (size_t)node * 128 + colb));
    for (int j = beg; j < end; j++) {
        int s = g_adj[j];
        float2 v = __half22float2(__ldg((const __half2*)(y + (size_t)s * 128 + colb)));
        acc.x += v.x; acc.y += v.y;
    }
    float d = g_dinv[node];
    *(__half2*)(out + (size_t)node * 128 + colb) = __floats2half2_rn(acc.x * d, acc.y * d);
}

__global__ void k_agg3f(const __half* __restrict__ y, float* __restrict__ out_mu,
                        const float* __restrict__ bm3, const float* __restrict__ bl3,
                        float* __restrict__ out_ls) {
    int gw = (blockIdx.x * blockDim.x + threadIdx.x) >> 5;
    if (gw >= NN) return;
    int lane = threadIdx.x & 31;
    int beg = g_off[gw], end = g_off[gw + 1];
    float2 acc = __half22float2(*(const __half2*)(y + gw * 64 + lane * 2));
    for (int j = beg; j < end; j++) {
        int s = g_adj[j];
        float2 v = __half22float2(__ldg((const __half2*)(y + s * 64 + lane * 2)));
        acc.x += v.x; acc.y += v.y;
    }
    float d = g_dinv[gw];
    acc.x *= d; acc.y *= d;
    int c = lane * 2;
    if (c < 32) {
        float m0 = acc.x + bm3[c];
        float m1 = acc.y + bm3[c + 1];
        out_mu[gw * 32 + c]     = m0;
        out_mu[gw * 32 + c + 1] = m1;
        *(__half2*)(g_muh + gw * 32 + c) = __floats2half2_rn(m0, m1);
    } else {
        out_ls[gw * 32 + c - 32] = fminf(acc.x + bl3[c - 32], 10.0f);
        out_ls[gw * 32 + c - 31] = fminf(acc.y + bl3[c - 31], 10.0f);
    }
}

// ---------------- layer-1 GEMM: HMMA (proven) ----------------
__global__ void __launch_bounds__(256) k_gemm1(
        const __half* __restrict__ A, const float* __restrict__ W1,
        const float* __restrict__ W2, const float* __restrict__ b1,
        const float* __restrict__ b2, __half* __restrict__ C) {
    extern __shared__ __align__(16) char smem1[];
    __half* Ah = (__half*)smem1;                      // [128][72]
    __half* Wh = (__half*)(smem1 + 128 * 72 * 2);     // [64][136]
    int tid = threadIdx.x;
    int row0 = blockIdx.x * 128;

    for (int i = tid; i < 4096; i += 256) {
        int k = i >> 6, n2 = i & 63;
        int n = n2 * 2;
        float2 wv = (n < 64) ? *(const float2*)(W1 + k * 64 + n)
                             : *(const float2*)(W2 + k * 64 + (n - 64));
        *(__half2*)(Wh + k * 136 + n) = __floats2half2_rn(wv.x, wv.y);
    }
    for (int i = tid; i < 2048; i += 256) {
        int r = i >> 4, q = i & 15;
        uint2 v = make_uint2(0u, 0u);
        if (row0 + r < NN) v = ((const uint2*)(A + (size_t)(row0 + r) * 64))[q];
        *(uint2*)(Ah + r * 72 + q * 4) = v;
    }
    __syncthreads();

    int warp = tid >> 5, lane = tid & 31;
    int R = warp * 16;
    float c[16][4];
    #pragma unroll
    for (int n0 = 0; n0 < 16; n0++)
        #pragma unroll
        for (int j = 0; j < 4; j++) c[n0][j] = 0.f;

    #pragma unroll
    for (int kc = 0; kc < 4; kc++) {
        u32 a0, a1, a2, a3;
        ldsm_x4(a0, a1, a2, a3,
                saddr(Ah + (R + (lane & 15)) * 72 + kc * 16 + (lane >> 4) * 8));
        #pragma unroll
        for (int n0 = 0; n0 < 16; n0++) {
            u32 b0, b1v;
            ldsm_x2t(b0, b1v, saddr(Wh + (kc * 16 + (lane & 15)) * 136 + n0 * 8));
            mma16816(c[n0][0], c[n0][1], c[n0][2], c[n0][3], a0, a1, a2, a3, b0, b1v);
        }
    }

    int rq = lane >> 2, cq = (lane & 3) * 2;
    int r0 = row0 + R + rq, r1 = r0 + 8;
    #pragma unroll
    for (int n0 = 0; n0 < 16; n0++) {
        int col = n0 * 8 + cq;
        float bb0 = (col < 64) ? b1[col] : b2[col - 64];
        float bb1 = (col < 64) ? b1[col + 1] : b2[col + 1 - 64];
        if (r0 < NN)
            *(__half2*)(C + (size_t)r0 * 128 + col) =
                __floats2half2_rn(c[n0][0] + bb0, c[n0][1] + bb1);
        if (r1 < NN)
            *(__half2*)(C + (size_t)r1 * 128 + col) =
                __floats2half2_rn(c[n0][2] + bb0, c[n0][3] + bb1);
    }
}

// ---------------- BN stats pass 1 ----------------
__global__ void __launch_bounds__(256) k_stats1() {
    __shared__ float red[256];
    int tid = threadIdx.x;
    int g = tid & 15, rsub = tid >> 4;
    int c0 = g * 8;
    bool rl = (c0 >= 64);
    int row0 = blockIdx.x * 128;
    float s[8], q[8];
    #pragma unroll
    for (int i = 0; i < 8; i++) { s[i] = 0.f; q[i] = 0.f; }
    for (int r = row0 + rsub; r < row0 + 128 && r < NN; r += 16) {
        uint4 u = *(const uint4*)(g_raw1h + (size_t)r * 128 + c0);
        u32 w[4] = {u.x, u.y, u.z, u.w};
        #pragma unroll
        for (int p = 0; p < 4; p++) {
            float2 f = __half22float2(*(__half2*)&w[p]);
            float v0 = rl ? fmaxf(f.x, 0.f) : f.x;
            float v1 = rl ? fmaxf(f.y, 0.f) : f.y;
            s[p * 2] += v0; q[p * 2] += v0 * v0;
            s[p * 2 + 1] += v1; q[p * 2 + 1] += v1 * v1;
        }
    }
    red[tid] = 0.f;
    __syncthreads();
    #pragma unroll
    for (int i = 0; i < 8; i++) {
        atomicAdd(&red[c0 + i], s[i]);
        atomicAdd(&red[128 + c0 + i], q[i]);
    }
    __syncthreads();
    if (tid < 128) {
        atomicAdd(&g_ssum[tid], red[tid]);
        atomicAdd(&g_ssq[tid], red[tid + 128]);
    }
}

// ---------------- BN stats pass 2 ----------------
__global__ void __launch_bounds__(256) k_stats2() {
    __shared__ float red[512];
    int tid = threadIdx.x;
    int g = tid & 31, rsub = tid >> 5;
    int c0 = g * 8;
    bool rl = (c0 >= 128);
    int row0 = blockIdx.x * 128;
    float s[8], q[8];
    #pragma unroll
    for (int i = 0; i < 8; i++) { s[i] = 0.f; q[i] = 0.f; }
    for (int r = row0 + rsub; r < row0 + 128 && r < NN; r += 8) {
        uint4 u = *(const uint4*)(g_raw2h + (size_t)r * 256 + c0);
        u32 w[4] = {u.x, u.y, u.z, u.w};
        #pragma unroll
        for (int p = 0; p < 4; p++) {
            float2 f = __half22float2(*(__half2*)&w[p]);
            float v0 = rl ? fmaxf(f.x, 0.f) : f.x;
            float v1 = rl ? fmaxf(f.y, 0.f) : f.y;
            s[p * 2] += v0; q[p * 2] += v0 * v0;
            s[p * 2 + 1] += v1; q[p * 2 + 1] += v1 * v1;
        }
    }
    red[tid] = 0.f; red[tid + 256] = 0.f;
    __syncthreads();
    #pragma unroll
    for (int i = 0; i < 8; i++) {
        atomicAdd(&red[c0 + i], s[i]);
        atomicAdd(&red[256 + c0 + i], q[i]);
    }
    __syncthreads();
    atomicAdd(&g_ssum[256 + tid], red[tid]);
    atomicAdd(&g_ssq[256 + tid], red[tid + 256]);
}

// elementwise layer1
__global__ void k_ew1(const float* __restrict__ g1, const float* __restrict__ h1,
                      const float* __restrict__ g2, const float* __restrict__ h2) {
    __shared__ float sa[128], sb[128];
    int tid = threadIdx.x;
    if (tid < 128) {
        float m = g_ssum[tid] * (1.0f / NN);
        float v = g_ssq[tid] * (1.0f / NN) - m * m;
        float rstd = rsqrtf(v + 1e-5f);
        float gamma = (tid < 64) ? g1[tid] : g2[tid - 64];
        float beta  = (tid < 64) ? h1[tid] : h2[tid - 64];
        float a = gamma * rstd;
        sa[tid] = a;
        sb[tid] = beta - m * a;
    }
    __syncthreads();
    int idx = blockIdx.x * blockDim.x + tid;
    if (idx >= NN * 32) return;
    int r = idx >> 5;
    int c4 = (idx & 31) << 2;
    uint2 u = ((const uint2*)g_raw1h)[idx];
    float2 v01 = __half22float2(*(__half2*)&u.x);
    float2 v23 = __half22float2(*(__half2*)&u.y);
    float d = g_dinv[r];
    float o[4]; float vv[4] = {v01.x, v01.y, v23.x, v23.y};
    #pragma unroll
    for (int t = 0; t < 4; t++) {
        int c = c4 + t;
        float a = sa[c], b = sb[c];
        if (c4 < 64) o[t] = fmaxf(vv[t] * a + b, 0.f);
        else         o[t] = fmaxf(vv[t], 0.f) * a + b;
        o[t] *= d;
    }
    __half2 h0 = __floats2half2_rn(o[0], o[1]);
    __half2 h1v = __floats2half2_rn(o[2], o[3]);
    ((uint2*)g_y1h)[idx] = make_uint2(*(unsigned*)&h0, *(unsigned*)&h1v);
}

// ---------------- layer-2 GEMM: HMMA (proven) ----------------
__global__ void __launch_bounds__(256) k_gemm2(
        const __half* __restrict__ A, const float* __restrict__ W1,
        const float* __restrict__ W2, const float* __restrict__ b1,
        const float* __restrict__ b2, __half* __restrict__ C) {
    extern __shared__ __align__(16) char smem2[];
    __half* Ah = (__half*)smem2;                       // [64][136]
    __half* Wh = (__half*)(smem2 + 64 * 136 * 2);      // [2][64][136]
    int tid = threadIdx.x;
    int row0 = blockIdx.x * 64;

    for (int i = tid; i < 8192; i += 256) {
        int h = i >> 12, j = i & 4095;
        int k = j >> 6, n2 = j & 63;
        int n = n2 * 2;
        const float* W = h ? W2 : W1;
        float2 wv = *(const float2*)(W + k * 128 + n);
        *(__half2*)(Wh + h * 64 * 136 + k * 136 + n) = __floats2half2_rn(wv.x, wv.y);
    }
    for (int i = tid; i < 2048; i += 256) {
        int r = i >> 5, q = i & 31;
        uint2 v = make_uint2(0u, 0u);
        if (row0 + r < NN) v = ((const uint2*)(A + (size_t)(row0 + r) * 128))[q];
        *(uint2*)(Ah + r * 136 + q * 4) = v;
    }
    __syncthreads();

    int warp = tid >> 5, lane = tid & 31;
    int h = warp >> 2;
    int R = (warp & 3) * 16;
    float c[16][4];
    #pragma unroll
    for (int n0 = 0; n0 < 16; n0++)
        #pragma unroll
        for (int j = 0; j < 4; j++) c[n0][j] = 0.f;

    #pragma unroll
    for (int kc = 0; kc < 4; kc++) {
        u32 a0, a1, a2, a3;
        ldsm_x4(a0, a1, a2, a3,
                saddr(Ah + (R + (lane & 15)) * 136 + h * 64 + kc * 16 + (lane >> 4) * 8));
        #pragma unroll
        for (int n0 = 0; n0 < 16; n0++) {
            u32 b0, b1v;
            ldsm_x2t(b0, b1v,
                     saddr(Wh + h * 64 * 136 + (kc * 16 + (lane & 15)) * 136 + n0 * 8));
            mma16816(c[n0][0], c[n0][1], c[n0][2], c[n0][3], a0, a1, a2, a3, b0, b1v);
        }
    }

    int rq = lane >> 2, cq = (lane & 3) * 2;
    int r0 = row0 + R + rq, r1 = r0 + 8;
    const float* bp = h ? b2 : b1;
    #pragma unroll
    for (int n0 = 0; n0 < 16; n0++) {
        int cl = n0 * 8 + cq;
        int cg = h * 128 + cl;
        float bb0 = bp[cl], bb1 = bp[cl + 1];
        if (r0 < NN)
            *(__half2*)(C + (size_t)r0 * 256 + cg) =
                __floats2half2_rn(c[n0][0] + bb0, c[n0][1] + bb1);
        if (r1 < NN)
            *(__half2*)(C + (size_t)r1 * 256 + cg) =
                __floats2half2_rn(c[n0][2] + bb0, c[n0][3] + bb1);
    }
}

// ---------------- layer-3 GEMM: HMMA, BN-on-load, statfin folded (R13 proven) ----------------
__global__ void __launch_bounds__(256) k_gemm3(
        const __half* __restrict__ raw2, const float* __restrict__ Wm3,
        const float* __restrict__ Wl3, __half* __restrict__ y3,
        const float* __restrict__ g1, const float* __restrict__ h1,
        const float* __restrict__ g2, const float* __restrict__ h2) {
    extern __shared__ __align__(16) char smem3[];
    __half* Ah = (__half*)smem3;                        // [128][264]
    __half* Wh = (__half*)(smem3 + 128 * 264 * 2);      // [2][128][40]
    float* sa = (float*)(smem3 + 128 * 264 * 2 + 2 * 128 * 40 * 2);  // [256]
    float* sb = sa + 256;                                              // [256]
    int tid = threadIdx.x;
    int row0 = blockIdx.x * 128;

    {
        float m = g_ssum[256 + tid] * (1.0f / NN);
        float v = g_ssq[256 + tid] * (1.0f / NN) - m * m;
        float rstd = rsqrtf(v + 1e-5f);
        float gamma = (tid < 128) ? g1[tid] : g2[tid - 128];
        float beta  = (tid < 128) ? h1[tid] : h2[tid - 128];
        float a = gamma * rstd;
        sa[tid] = a;
        sb[tid] = beta - m * a;
    }

    for (int i = tid; i < 4096; i += 256) {
        int h = i >> 11, j = i & 2047;
        int k = j >> 4, n2 = j & 15;
        int n = n2 * 2;
        const float* W = h ? Wl3 : Wm3;
        float2 wv = *(const float2*)(W + k * 32 + n);
        *(__half2*)(Wh + h * 128 * 40 + k * 40 + n) = __floats2half2_rn(wv.x, wv.y);
    }
    __syncthreads();

    for (int i = tid; i < 8192; i += 256) {
        int r = i >> 6, q = i & 63;
        int c4 = q * 4;
        int half = (c4 >= 128) ? 1 : 0;
        uint2 u = make_uint2(0u, 0u);
        if (row0 + r < NN)
            u = ((const uint2*)(raw2 + (size_t)(row0 + r) * 256))[q];
        float2 p01 = __half22float2(*(__half2*)&u.x);
        float2 p23 = __half22float2(*(__half2*)&u.y);
        float vv[4] = {p01.x, p01.y, p23.x, p23.y};
        float o[4];
        #pragma unroll
        for (int t = 0; t < 4; t++) {
            int col = c4 + t;
            float a = sa[col], b = sb[col];
            if (half == 0) o[t] = fmaxf(vv[t] * a + b, 0.f);
            else           o[t] = fmaxf(vv[t], 0.f) * a + b;
        }
        __half2 ha = __floats2half2_rn(o[0], o[1]);
        __half2 hb = __floats2half2_rn(o[2], o[3]);
        *(uint2*)(Ah + r * 264 + c4) = make_uint2(*(unsigned*)&ha, *(unsigned*)&hb);
    }
    __syncthreads();

    int warp = tid >> 5, lane = tid & 31;
    int h = warp >> 2;
    int R = (warp & 3) * 32;
    float c[2][4][4];
    #pragma unroll
    for (int m = 0; m < 2; m++)
        #pragma unroll
        for (int n0 = 0; n0 < 4; n0++)
            #pragma unroll
            for (int j = 0; j < 4; j++) c[m][n0][j] = 0.f;

    #pragma unroll
    for (int kc = 0; kc < 8; kc++) {
        u32 b0[4], b1v[4];
        #pragma unroll
        for (int n0 = 0; n0 < 4; n0++)
            ldsm_x2t(b0[n0], b1v[n0],
                     saddr(Wh + h * 128 * 40 + (kc * 16 + (lane & 15)) * 40 + n0 * 8));
        #pragma unroll
        for (int m = 0; m < 2; m++) {
            u32 a0, a1, a2, a3;
            ldsm_x4(a0, a1, a2, a3,
                    saddr(Ah + (R + m * 16 + (lane & 15)) * 264 + h * 128 + kc * 16 + (lane >> 4) * 8));
            #pragma unroll
            for (int n0 = 0; n0 < 4; n0++)
                mma16816(c[m][n0][0], c[m][n0][1], c[m][n0][2], c[m][n0][3],
                         a0, a1, a2, a3, b0[n0], b1v[n0]);
        }
    }

    int rq = lane >> 2, cq = (lane & 3) * 2;
    #pragma unroll
    for (int m = 0; m < 2; m++) {
        int r0 = row0 + R + m * 16 + rq, r1 = r0 + 8;
        #pragma unroll
        for (int n0 = 0; n0 < 4; n0++) {
            int col = h * 32 + n0 * 8 + cq;
            if (r0 < NN) {
                float d = g_dinv[r0];
                *(__half2*)(y3 + (size_t)r0 * 64 + col) =
                    __floats2half2_rn(c[m][n0][0] * d, c[m][n0][1] * d);
            }
            if (r1 < NN) {
                float d = g_dinv[r1];
                *(__half2*)(y3 + (size_t)r1 * 64 + col) =
                    __floats2half2_rn(c[m][n0][2] * d, c[m][n0][3] * d);
            }
        }
    }
}

// ---------------- decoder ----------------
__global__ void k_dec(const int* __restrict__ src, const int* __restrict__ dst,
                      const __half* __restrict__ muh, float* __restrict__ probs) {
    int t = blockIdx.x * blockDim.x + threadIdx.x;
    int e = t >> 2, sub = t & 3;
    int s = src[e], d = dst[e];
    uint4 ua = __ldg((const uint4*)(muh + s * 32 + sub * 8));
    uint4 ub = __ldg((const uint4*)(muh + d * 32 + sub * 8));
    float p = 0.f;
    {
        float2 fa, fb;
        fa = __half22float2(*(__half2*)&ua.x); fb = __half22float2(*(__half2*)&ub.x);
        p += fa.x * fb.x + fa.y * fb.y;
        fa = __half22float2(*(__half2*)&ua.y); fb = __half22float2(*(__half2*)&ub.y);
        p += fa.x * fb.x + fa.y * fb.y;
        fa = __half22float2(*(__half2*)&ua.z); fb = __half22float2(*(__half2*)&ub.z);
        p += fa.x * fb.x + fa.y * fb.y;
        fa = __half22float2(*(__half2*)&ua.w); fb = __half22float2(*(__half2*)&ub.w);
        p += fa.x * fb.x + fa.y * fb.y;
    }
    p += __shfl_down_sync(~0u, p, 2);
    p += __shfl_down_sync(~0u, p, 1);
    if (sub == 0) probs[e] = 1.f / (1.f + expf(-p));
}

// ---------------- launch ----------------
extern "C" void kernel_launch(void* const* d_in, const int* in_sizes, int n_in,
                              void* d_out, int out_size) {
    const float* x   = (const float*)d_in[0];
    const int* ei    = (const int*)d_in[1];
    const int* src   = ei;
    const int* dst   = ei + EE;
    const float* Wm1 = (const float*)d_in[2];
    const float* bm1 = (const float*)d_in[3];
    const float* gm1 = (const float*)d_in[4];
    const float* hm1 = (const float*)d_in[5];
    const float* Wm2 = (const float*)d_in[6];
    const float* bm2 = (const float*)d_in[7];
    const float* gm2 = (const float*)d_in[8];
    const float* hm2 = (const float*)d_in[9];
    const float* Wm3 = (const float*)d_in[10];
    const float* bm3 = (const float*)d_in[11];
    const float* Wl1 = (const float*)d_in[12];
    const float* bl1 = (const float*)d_in[13];
    const float* gl1 = (const float*)d_in[14];
    const float* hl1 = (const float*)d_in[15];
    const float* Wl2 = (const float*)d_in[16];
    const float* bl2 = (const float*)d_in[17];
    const float* gl2 = (const float*)d_in[18];
    const float* hl2 = (const float*)d_in[19];
    const float* Wl3 = (const float*)d_in[20];
    const float* bl3 = (const float*)d_in[21];

    float* out = (float*)d_out;
    float* out_probs = out;
    float* out_mu = out + EE;
    float* out_ls = out + EE + NN * 32;

    __half *y0h, *axh, *raw1h, *y1h, *agg1h, *raw2h, *y3h, *muh;
    cudaGetSymbolAddress((void**)&y0h, g_y0h);
    cudaGetSymbolAddress((void**)&axh, g_axh);
    cudaGetSymbolAddress((void**)&raw1h, g_raw1h);
    cudaGetSymbolAddress((void**)&y1h, g_y1h);
    cudaGetSymbolAddress((void**)&agg1h, g_agg1h);
    cudaGetSymbolAddress((void**)&raw2h, g_raw2h);
    cudaGetSymbolAddress((void**)&y3h, g_y3h);
    cudaGetSymbolAddress((void**)&muh, g_muh);

    const int SM1 = 128 * 72 * 2 + 64 * 136 * 2;                       // 35,840
    const int SM2 = 64 * 136 * 2 + 2 * 64 * 136 * 2;                   // 52,224
    const int SM3 = 128 * 264 * 2 + 2 * 128 * 40 * 2 + 512 * 4;        // 90,112
    cudaFuncSetAttribute(k_gemm1, cudaFuncAttributeMaxDynamicSharedMemorySize, SM1);
    cudaFuncSetAttribute(k_gemm2, cudaFuncAttributeMaxDynamicSharedMemorySize, SM2);
    cudaFuncSetAttribute(k_gemm3, cudaFuncAttributeMaxDynamicSharedMemorySize, SM3);

    // setup + degree + CSR
    k_zero<<<196, 256>>>();
    k_indeg<<<3125, 256>>>(dst);
    k_dinv_y0<<<3125, 256>>>(x);
    k_scan1<<<49, 1024>>>();
    k_scan3<<<49, 1024>>>();
    k_scatter<<<3125, 256>>>(src, dst);

    // layer 1
    k_agg1h<<<6250, 256>>>(y0h, axh);
    k_gemm1<<<391, 256, SM1>>>(axh, Wm1, Wl1, bm1, bl1, raw1h);
    k_stats1<<<391, 256>>>();
    k_ew1<<<6250, 256>>>(gm1, hm1, gl1, hl1);

    // layer 2 (agg2: 2 warps/node)
    k_agg2h<<<12500, 256>>>(y1h, agg1h);
    k_gemm2<<<782, 256, SM2>>>(agg1h, Wm2, Wl2, bm2, bl2, raw2h);
    k_stats2<<<391, 256>>>();

    // layer 3
    k_gemm3<<<391, 256, SM3>>>(raw2h, Wm3, Wl3, y3h, gm2, hm2, gl2, hl2);
    k_agg3f<<<6250, 256>>>(y3h, out_mu, bm3, bl3, out_ls);

    // decoder
    k_dec<<<12500, 256>>>(src, dst, muh, out_probs);
}

// round 15
// speedup vs baseline: 1.0398x; 1.0398x over previous
#include <cuda_runtime.h>
#include <cuda_fp16.h>
#include <cstdint>

#define NN 50000
#define EE 800000

typedef unsigned long long ull;
typedef unsigned int u32;

__device__ __forceinline__ u32 saddr(const void* p) {
    return (u32)__cvta_generic_to_shared(p);
}
__device__ __forceinline__ void ldsm_x4(u32 &a0, u32 &a1, u32 &a2, u32 &a3, u32 addr) {
    asm volatile("ldmatrix.sync.aligned.m8n8.x4.shared.b16 {%0,%1,%2,%3}, [%4];"
                 : "=r"(a0), "=r"(a1), "=r"(a2), "=r"(a3) : "r"(addr));
}
__device__ __forceinline__ void ldsm_x2t(u32 &b0, u32 &b1, u32 addr) {
    asm volatile("ldmatrix.sync.aligned.m8n8.x2.trans.shared.b16 {%0,%1}, [%2];"
                 : "=r"(b0), "=r"(b1) : "r"(addr));
}
__device__ __forceinline__ void mma16816(float &c0, float &c1, float &c2, float &c3,
                                         u32 a0, u32 a1, u32 a2, u32 a3,
                                         u32 b0, u32 b1) {
    asm volatile(
        "mma.sync.aligned.m16n8k16.row.col.f32.f16.f16.f32 "
        "{%0,%1,%2,%3}, {%4,%5,%6,%7}, {%8,%9}, {%0,%1,%2,%3};"
        : "+f"(c0), "+f"(c1), "+f"(c2), "+f"(c3)
        : "r"(a0), "r"(a1), "r"(a2), "r"(a3), "r"(b0), "r"(b1));
}

// ---------------- scratch ----------------
__device__ float g_dinv[NN];
__device__ int   g_indeg[NN];
__device__ int   g_cur[NN];
__device__ int   g_off[NN + 1];
__device__ int   g_adj[EE];
__device__ int   g_bsum[64];

__device__ __half g_y0h[NN * 64];
__device__ __half g_axh[NN * 64];
__device__ __half g_raw1h[NN * 128];
__device__ __half g_y1h[NN * 128];
__device__ __half g_agg1h[NN * 128];
__device__ __half g_raw2h[NN * 256];
__device__ __half g_y3h[NN * 64];
__device__ __half g_muh[NN * 32];

__device__ float g_ssum[512];
__device__ float g_ssq[512];

// ---------------- degree ----------------
// g_indeg is zero on entry: zero-initialized at load, re-zeroed by k_agg1h each call.
__global__ void k_indeg(const int* __restrict__ dst) {
    int e = blockIdx.x * blockDim.x + threadIdx.x;
    if (e < EE) atomicAdd(&g_indeg[dst[e]], 1);
}

// ---------------- fused scan + dinv/y0 ----------------
// blocks 0..48: exclusive-scan prep of g_off (1024 threads each)
// blocks 49..830: dinv + y0h fill (NN*16 float4 items)
__global__ void k_scan1(const float* __restrict__ x) {
    int bid = blockIdx.x;
    if (bid < 49) {
        int i = bid * 1024 + threadIdx.x;
        int v = (i < NN) ? g_indeg[i] : 0;
        int lane = threadIdx.x & 31, wid = threadIdx.x >> 5;
        int s = v;
        #pragma unroll
        for (int o = 1; o < 32; o <<= 1) {
            int t = __shfl_up_sync(~0u, s, o);
            if (lane >= o) s += t;
        }
        __shared__ int wsum[32];
        if (lane == 31) wsum[wid] = s;
        __syncthreads();
        if (wid == 0) {
            int ws = wsum[lane];
            #pragma unroll
            for (int o = 1; o < 32; o <<= 1) {
                int t = __shfl_up_sync(~0u, ws, o);
                if (lane >= o) ws += t;
            }
            wsum[lane] = ws;
        }
        __syncthreads();
        int incl = s + (wid > 0 ? wsum[wid - 1] : 0);
        if (i < NN) g_off[i + 1] = incl;
        if (threadIdx.x == 1023) g_bsum[bid] = incl;
    } else {
        int idx = (bid - 49) * 1024 + threadIdx.x;
        if (idx < NN * 16) {
            int row = idx >> 4;
            float d = rsqrtf((float)(g_indeg[row] + 1));
            if ((idx & 15) == 0) g_dinv[row] = d;
            float4 v = ((const float4*)x)[idx];
            __half2 h0 = __floats2half2_rn(v.x * d, v.y * d);
            __half2 h1 = __floats2half2_rn(v.z * d, v.w * d);
            ((uint2*)g_y0h)[idx] = make_uint2(*(unsigned*)&h0, *(unsigned*)&h1);
        }
    }
}

__global__ void k_scan3() {
    __shared__ int base;
    if (threadIdx.x == 0) {
        int acc = 0;
        for (int b = 0; b < blockIdx.x; b++) acc += g_bsum[b];
        base = acc;
    }
    __syncthreads();
    int i = blockIdx.x * 1024 + threadIdx.x;
    if (i < NN) g_off[i + 1] += base;
    if (i == 0) g_off[0] = 0;
}

// g_cur is zero on entry (re-zeroed by k_stats1 each call)
__global__ void k_scatter(const int* __restrict__ src, const int* __restrict__ dst) {
    int e = blockIdx.x * blockDim.x + threadIdx.x;
    if (e < EE) {
        int d = dst[e];
        int p = g_off[d] + atomicAdd(&g_cur[d], 1);
        g_adj[p] = src[e];
    }
}

// ---------------- aggregations (R13 proven) ----------------
// also re-zeroes g_indeg for the next call (last read was dinv in k_scan1)
__global__ void k_agg1h(const __half* __restrict__ y, __half* __restrict__ out) {
    int tid = blockIdx.x * blockDim.x + threadIdx.x;
    if (tid < NN) g_indeg[tid] = 0;
    int gw = tid >> 5;
    if (gw >= NN) return;
    int lane = threadIdx.x & 31;
    int beg = g_off[gw], end = g_off[gw + 1];
    float2 acc = __half22float2(*(const __half2*)(y + gw * 64 + lane * 2));
    for (int j = beg; j < end; j++) {
        int s = g_adj[j];
        float2 v = __half22float2(__ldg((const __half2*)(y + s * 64 + lane * 2)));
        acc.x += v.x; acc.y += v.y;
    }
    float d = g_dinv[gw];
    *(__half2*)(out + gw * 64 + lane * 2) = __floats2half2_rn(acc.x * d, acc.y * d);
}

// also re-zeroes g_ssum/g_ssq[0:128] (last read: k_ew1, which runs before this)
__global__ void k_agg2h(const __half* __restrict__ y, __half* __restrict__ out) {
    int tid = blockIdx.x * blockDim.x + threadIdx.x;
    if (tid < 128) { g_ssum[tid] = 0.f; g_ssq[tid] = 0.f; }
    int gw = tid >> 5;
    if (gw >= NN) return;
    int lane = threadIdx.x & 31;
    int beg = g_off[gw], end = g_off[gw + 1];
    uint2 u0 = *(const uint2*)(y + (size_t)gw * 128 + lane * 4);
    float2 a01 = __half22float2(*(__half2*)&u0.x);
    float2 a23 = __half22float2(*(__half2*)&u0.y);
    float4 acc = make_float4(a01.x, a01.y, a23.x, a23.y);
    for (int j = beg; j < end; j++) {
        int s = g_adj[j];
        uint2 u = __ldg((const uint2*)(y + (size_t)s * 128 + lane * 4));
        float2 f01 = __half22float2(*(__half2*)&u.x);
        float2 f23 = __half22float2(*(__half2*)&u.y);
        acc.x += f01.x; acc.y += f01.y; acc.z += f23.x; acc.w += f23.y;
    }
    float d = g_dinv[gw];
    __half2 h0 = __floats2half2_rn(acc.x * d, acc.y * d);
    __half2 h1 = __floats2half2_rn(acc.z * d, acc.w * d);
    *(uint2*)(out + (size_t)gw * 128 + lane * 4) = make_uint2(*(unsigned*)&h0, *(unsigned*)&h1);
}

// also re-zeroes g_ssum/g_ssq[256:512] (last read: k_gemm3, which runs before this)
__global__ void k_agg3f(const __half* __restrict__ y, float* __restrict__ out_mu,
                        const float* __restrict__ bm3, const float* __restrict__ bl3,
                        float* __restrict__ out_ls) {
    int tid = blockIdx.x * blockDim.x + threadIdx.x;
    if (tid < 256) { g_ssum[256 + tid] = 0.f; g_ssq[256 + tid] = 0.f; }
    int gw = tid >> 5;
    if (gw >= NN) return;
    int lane = threadIdx.x & 31;
    int beg = g_off[gw], end = g_off[gw + 1];
    float2 acc = __half22float2(*(const __half2*)(y + gw * 64 + lane * 2));
    for (int j = beg; j < end; j++) {
        int s = g_adj[j];
        float2 v = __half22float2(__ldg((const __half2*)(y + s * 64 + lane * 2)));
        acc.x += v.x; acc.y += v.y;
    }
    float d = g_dinv[gw];
    acc.x *= d; acc.y *= d;
    int c = lane * 2;
    if (c < 32) {
        float m0 = acc.x + bm3[c];
        float m1 = acc.y + bm3[c + 1];
        out_mu[gw * 32 + c]     = m0;
        out_mu[gw * 32 + c + 1] = m1;
        *(__half2*)(g_muh + gw * 32 + c) = __floats2half2_rn(m0, m1);
    } else {
        out_ls[gw * 32 + c - 32] = fminf(acc.x + bl3[c - 32], 10.0f);
        out_ls[gw * 32 + c - 31] = fminf(acc.y + bl3[c - 31], 10.0f);
    }
}

// ---------------- layer-1 GEMM: HMMA (proven) ----------------
__global__ void __launch_bounds__(256) k_gemm1(
        const __half* __restrict__ A, const float* __restrict__ W1,
        const float* __restrict__ W2, const float* __restrict__ b1,
        const float* __restrict__ b2, __half* __restrict__ C) {
    extern __shared__ __align__(16) char smem1[];
    __half* Ah = (__half*)smem1;                      // [128][72]
    __half* Wh = (__half*)(smem1 + 128 * 72 * 2);     // [64][136]
    int tid = threadIdx.x;
    int row0 = blockIdx.x * 128;

    for (int i = tid; i < 4096; i += 256) {
        int k = i >> 6, n2 = i & 63;
        int n = n2 * 2;
        float2 wv = (n < 64) ? *(const float2*)(W1 + k * 64 + n)
                             : *(const float2*)(W2 + k * 64 + (n - 64));
        *(__half2*)(Wh + k * 136 + n) = __floats2half2_rn(wv.x, wv.y);
    }
    for (int i = tid; i < 2048; i += 256) {
        int r = i >> 4, q = i & 15;
        uint2 v = make_uint2(0u, 0u);
        if (row0 + r < NN) v = ((const uint2*)(A + (size_t)(row0 + r) * 64))[q];
        *(uint2*)(Ah + r * 72 + q * 4) = v;
    }
    __syncthreads();

    int warp = tid >> 5, lane = tid & 31;
    int R = warp * 16;
    float c[16][4];
    #pragma unroll
    for (int n0 = 0; n0 < 16; n0++)
        #pragma unroll
        for (int j = 0; j < 4; j++) c[n0][j] = 0.f;

    #pragma unroll
    for (int kc = 0; kc < 4; kc++) {
        u32 a0, a1, a2, a3;
        ldsm_x4(a0, a1, a2, a3,
                saddr(Ah + (R + (lane & 15)) * 72 + kc * 16 + (lane >> 4) * 8));
        #pragma unroll
        for (int n0 = 0; n0 < 16; n0++) {
            u32 b0, b1v;
            ldsm_x2t(b0, b1v, saddr(Wh + (kc * 16 + (lane & 15)) * 136 + n0 * 8));
            mma16816(c[n0][0], c[n0][1], c[n0][2], c[n0][3], a0, a1, a2, a3, b0, b1v);
        }
    }

    int rq = lane >> 2, cq = (lane & 3) * 2;
    int r0 = row0 + R + rq, r1 = r0 + 8;
    #pragma unroll
    for (int n0 = 0; n0 < 16; n0++) {
        int col = n0 * 8 + cq;
        float bb0 = (col < 64) ? b1[col] : b2[col - 64];
        float bb1 = (col < 64) ? b1[col + 1] : b2[col + 1 - 64];
        if (r0 < NN)
            *(__half2*)(C + (size_t)r0 * 128 + col) =
                __floats2half2_rn(c[n0][0] + bb0, c[n0][1] + bb1);
        if (r1 < NN)
            *(__half2*)(C + (size_t)r1 * 128 + col) =
                __floats2half2_rn(c[n0][2] + bb0, c[n0][3] + bb1);
    }
}

// ---------------- BN stats pass 1 (also re-zeroes g_cur) ----------------
__global__ void __launch_bounds__(256) k_stats1() {
    __shared__ float red[256];
    int tid = threadIdx.x;
    int gid = blockIdx.x * 256 + tid;
    if (gid < NN) g_cur[gid] = 0;
    int g = tid & 15, rsub = tid >> 4;
    int c0 = g * 8;
    bool rl = (c0 >= 64);
    int row0 = blockIdx.x * 128;
    float s[8], q[8];
    #pragma unroll
    for (int i = 0; i < 8; i++) { s[i] = 0.f; q[i] = 0.f; }
    for (int r = row0 + rsub; r < row0 + 128 && r < NN; r += 16) {
        uint4 u = *(const uint4*)(g_raw1h + (size_t)r * 128 + c0);
        u32 w[4] = {u.x, u.y, u.z, u.w};
        #pragma unroll
        for (int p = 0; p < 4; p++) {
            float2 f = __half22float2(*(__half2*)&w[p]);
            float v0 = rl ? fmaxf(f.x, 0.f) : f.x;
            float v1 = rl ? fmaxf(f.y, 0.f) : f.y;
            s[p * 2] += v0; q[p * 2] += v0 * v0;
            s[p * 2 + 1] += v1; q[p * 2 + 1] += v1 * v1;
        }
    }
    red[tid] = 0.f;
    __syncthreads();
    #pragma unroll
    for (int i = 0; i < 8; i++) {
        atomicAdd(&red[c0 + i], s[i]);
        atomicAdd(&red[128 + c0 + i], q[i]);
    }
    __syncthreads();
    if (tid < 128) {
        atomicAdd(&g_ssum[tid], red[tid]);
        atomicAdd(&g_ssq[tid], red[tid + 128]);
    }
}

// ---------------- BN stats pass 2 ----------------
__global__ void __launch_bounds__(256) k_stats2() {
    __shared__ float red[512];
    int tid = threadIdx.x;
    int g = tid & 31, rsub = tid >> 5;
    int c0 = g * 8;
    bool rl = (c0 >= 128);
    int row0 = blockIdx.x * 128;
    float s[8], q[8];
    #pragma unroll
    for (int i = 0; i < 8; i++) { s[i] = 0.f; q[i] = 0.f; }
    for (int r = row0 + rsub; r < row0 + 128 && r < NN; r += 8) {
        uint4 u = *(const uint4*)(g_raw2h + (size_t)r * 256 + c0);
        u32 w[4] = {u.x, u.y, u.z, u.w};
        #pragma unroll
        for (int p = 0; p < 4; p++) {
            float2 f = __half22float2(*(__half2*)&w[p]);
            float v0 = rl ? fmaxf(f.x, 0.f) : f.x;
            float v1 = rl ? fmaxf(f.y, 0.f) : f.y;
            s[p * 2] += v0; q[p * 2] += v0 * v0;
            s[p * 2 + 1] += v1; q[p * 2 + 1] += v1 * v1;
        }
    }
    red[tid] = 0.f; red[tid + 256] = 0.f;
    __syncthreads();
    #pragma unroll
    for (int i = 0; i < 8; i++) {
        atomicAdd(&red[c0 + i], s[i]);
        atomicAdd(&red[256 + c0 + i], q[i]);
    }
    __syncthreads();
    atomicAdd(&g_ssum[256 + tid], red[tid]);
    atomicAdd(&g_ssq[256 + tid], red[tid + 256]);
}

// elementwise layer1
__global__ void k_ew1(const float* __restrict__ g1, const float* __restrict__ h1,
                      const float* __restrict__ g2, const float* __restrict__ h2) {
    __shared__ float sa[128], sb[128];
    int tid = threadIdx.x;
    if (tid < 128) {
        float m = g_ssum[tid] * (1.0f / NN);
        float v = g_ssq[tid] * (1.0f / NN) - m * m;
        float rstd = rsqrtf(v + 1e-5f);
        float gamma = (tid < 64) ? g1[tid] : g2[tid - 64];
        float beta  = (tid < 64) ? h1[tid] : h2[tid - 64];
        float a = gamma * rstd;
        sa[tid] = a;
        sb[tid] = beta - m * a;
    }
    __syncthreads();
    int idx = blockIdx.x * blockDim.x + tid;
    if (idx >= NN * 32) return;
    int r = idx >> 5;
    int c4 = (idx & 31) << 2;
    uint2 u = ((const uint2*)g_raw1h)[idx];
    float2 v01 = __half22float2(*(__half2*)&u.x);
    float2 v23 = __half22float2(*(__half2*)&u.y);
    float d = g_dinv[r];
    float o[4]; float vv[4] = {v01.x, v01.y, v23.x, v23.y};
    #pragma unroll
    for (int t = 0; t < 4; t++) {
        int c = c4 + t;
        float a = sa[c], b = sb[c];
        if (c4 < 64) o[t] = fmaxf(vv[t] * a + b, 0.f);
        else         o[t] = fmaxf(vv[t], 0.f) * a + b;
        o[t] *= d;
    }
    __half2 h0 = __floats2half2_rn(o[0], o[1]);
    __half2 h1v = __floats2half2_rn(o[2], o[3]);
    ((uint2*)g_y1h)[idx] = make_uint2(*(unsigned*)&h0, *(unsigned*)&h1v);
}

// ---------------- layer-2 GEMM: HMMA (proven) ----------------
__global__ void __launch_bounds__(256) k_gemm2(
        const __half* __restrict__ A, const float* __restrict__ W1,
        const float* __restrict__ W2, const float* __restrict__ b1,
        const float* __restrict__ b2, __half* __restrict__ C) {
    extern __shared__ __align__(16) char smem2[];
    __half* Ah = (__half*)smem2;                       // [64][136]
    __half* Wh = (__half*)(smem2 + 64 * 136 * 2);      // [2][64][136]
    int tid = threadIdx.x;
    int row0 = blockIdx.x * 64;

    for (int i = tid; i < 8192; i += 256) {
        int h = i >> 12, j = i & 4095;
        int k = j >> 6, n2 = j & 63;
        int n = n2 * 2;
        const float* W = h ? W2 : W1;
        float2 wv = *(const float2*)(W + k * 128 + n);
        *(__half2*)(Wh + h * 64 * 136 + k * 136 + n) = __floats2half2_rn(wv.x, wv.y);
    }
    for (int i = tid; i < 2048; i += 256) {
        int r = i >> 5, q = i & 31;
        uint2 v = make_uint2(0u, 0u);
        if (row0 + r < NN) v = ((const uint2*)(A + (size_t)(row0 + r) * 128))[q];
        *(uint2*)(Ah + r * 136 + q * 4) = v;
    }
    __syncthreads();

    int warp = tid >> 5, lane = tid & 31;
    int h = warp >> 2;
    int R = (warp & 3) * 16;
    float c[16][4];
    #pragma unroll
    for (int n0 = 0; n0 < 16; n0++)
        #pragma unroll
        for (int j = 0; j < 4; j++) c[n0][j] = 0.f;

    #pragma unroll
    for (int kc = 0; kc < 4; kc++) {
        u32 a0, a1, a2, a3;
        ldsm_x4(a0, a1, a2, a3,
                saddr(Ah + (R + (lane & 15)) * 136 + h * 64 + kc * 16 + (lane >> 4) * 8));
        #pragma unroll
        for (int n0 = 0; n0 < 16; n0++) {
            u32 b0, b1v;
            ldsm_x2t(b0, b1v,
                     saddr(Wh + h * 64 * 136 + (kc * 16 + (lane & 15)) * 136 + n0 * 8));
            mma16816(c[n0][0], c[n0][1], c[n0][2], c[n0][3], a0, a1, a2, a3, b0, b1v);
        }
    }

    int rq = lane >> 2, cq = (lane & 3) * 2;
    int r0 = row0 + R + rq, r1 = r0 + 8;
    const float* bp = h ? b2 : b1;
    #pragma unroll
    for (int n0 = 0; n0 < 16; n0++) {
        int cl = n0 * 8 + cq;
        int cg = h * 128 + cl;
        float bb0 = bp[cl], bb1 = bp[cl + 1];
        if (r0 < NN)
            *(__half2*)(C + (size_t)r0 * 256 + cg) =
                __floats2half2_rn(c[n0][0] + bb0, c[n0][1] + bb1);
        if (r1 < NN)
            *(__half2*)(C + (size_t)r1 * 256 + cg) =
                __floats2half2_rn(c[n0][2] + bb0, c[n0][3] + bb1);
    }
}

// ---------------- layer-3 GEMM: HMMA, BN-on-load, statfin folded (proven) ----------------
__global__ void __launch_bounds__(256) k_gemm3(
        const __half* __restrict__ raw2, const float* __restrict__ Wm3,
        const float* __restrict__ Wl3, __half* __restrict__ y3,
        const float* __restrict__ g1, const float* __restrict__ h1,
        const float* __restrict__ g2, const float* __restrict__ h2) {
    extern __shared__ __align__(16) char smem3[];
    __half* Ah = (__half*)smem3;                        // [128][264]
    __half* Wh = (__half*)(smem3 + 128 * 264 * 2);      // [2][128][40]
    float* sa = (float*)(smem3 + 128 * 264 * 2 + 2 * 128 * 40 * 2);  // [256]
    float* sb = sa + 256;                                              // [256]
    int tid = threadIdx.x;
    int row0 = blockIdx.x * 128;

    {
        float m = g_ssum[256 + tid] * (1.0f / NN);
        float v = g_ssq[256 + tid] * (1.0f / NN) - m * m;
        float rstd = rsqrtf(v + 1e-5f);
        float gamma = (tid < 128) ? g1[tid] : g2[tid - 128];
        float beta  = (tid < 128) ? h1[tid] : h2[tid - 128];
        float a = gamma * rstd;
        sa[tid] = a;
        sb[tid] = beta - m * a;
    }

    for (int i = tid; i < 4096; i += 256) {
        int h = i >> 11, j = i & 2047;
        int k = j >> 4, n2 = j & 15;
        int n = n2 * 2;
        const float* W = h ? Wl3 : Wm3;
        float2 wv = *(const float2*)(W + k * 32 + n);
        *(__half2*)(Wh + h * 128 * 40 + k * 40 + n) = __floats2half2_rn(wv.x, wv.y);
    }
    __syncthreads();

    for (int i = tid; i < 8192; i += 256) {
        int r = i >> 6, q = i & 63;
        int c4 = q * 4;
        int half = (c4 >= 128) ? 1 : 0;
        uint2 u = make_uint2(0u, 0u);
        if (row0 + r < NN)
            u = ((const uint2*)(raw2 + (size_t)(row0 + r) * 256))[q];
        float2 p01 = __half22float2(*(__half2*)&u.x);
        float2 p23 = __half22float2(*(__half2*)&u.y);
        float vv[4] = {p01.x, p01.y, p23.x, p23.y};
        float o[4];
        #pragma unroll
        for (int t = 0; t < 4; t++) {
            int col = c4 + t;
            float a = sa[col], b = sb[col];
            if (half == 0) o[t] = fmaxf(vv[t] * a + b, 0.f);
            else           o[t] = fmaxf(vv[t], 0.f) * a + b;
        }
        __half2 ha = __floats2half2_rn(o[0], o[1]);
        __half2 hb = __floats2half2_rn(o[2], o[3]);
        *(uint2*)(Ah + r * 264 + c4) = make_uint2(*(unsigned*)&ha, *(unsigned*)&hb);
    }
    __syncthreads();

    int warp = tid >> 5, lane = tid & 31;
    int h = warp >> 2;
    int R = (warp & 3) * 32;
    float c[2][4][4];
    #pragma unroll
    for (int m = 0; m < 2; m++)
        #pragma unroll
        for (int n0 = 0; n0 < 4; n0++)
            #pragma unroll
            for (int j = 0; j < 4; j++) c[m][n0][j] = 0.f;

    #pragma unroll
    for (int kc = 0; kc < 8; kc++) {
        u32 b0[4], b1v[4];
        #pragma unroll
        for (int n0 = 0; n0 < 4; n0++)
            ldsm_x2t(b0[n0], b1v[n0],
                     saddr(Wh + h * 128 * 40 + (kc * 16 + (lane & 15)) * 40 + n0 * 8));
        #pragma unroll
        for (int m = 0; m < 2; m++) {
            u32 a0, a1, a2, a3;
            ldsm_x4(a0, a1, a2, a3,
                    saddr(Ah + (R + m * 16 + (lane & 15)) * 264 + h * 128 + kc * 16 + (lane >> 4) * 8));
            #pragma unroll
            for (int n0 = 0; n0 < 4; n0++)
                mma16816(c[m][n0][0], c[m][n0][1], c[m][n0][2], c[m][n0][3],
                         a0, a1, a2, a3, b0[n0], b1v[n0]);
        }
    }

    int rq = lane >> 2, cq = (lane & 3) * 2;
    #pragma unroll
    for (int m = 0; m < 2; m++) {
        int r0 = row0 + R + m * 16 + rq, r1 = r0 + 8;
        #pragma unroll
        for (int n0 = 0; n0 < 4; n0++) {
            int col = h * 32 + n0 * 8 + cq;
            if (r0 < NN) {
                float d = g_dinv[r0];
                *(__half2*)(y3 + (size_t)r0 * 64 + col) =
                    __floats2half2_rn(c[m][n0][0] * d, c[m][n0][1] * d);
            }
            if (r1 < NN) {
                float d = g_dinv[r1];
                *(__half2*)(y3 + (size_t)r1 * 64 + col) =
                    __floats2half2_rn(c[m][n0][2] * d, c[m][n0][3] * d);
            }
        }
    }
}

// ---------------- decoder ----------------
__global__ void k_dec(const int* __restrict__ src, const int* __restrict__ dst,
                      const __half* __restrict__ muh, float* __restrict__ probs) {
    int t = blockIdx.x * blockDim.x + threadIdx.x;
    int e = t >> 2, sub = t & 3;
    int s = src[e], d = dst[e];
    uint4 ua = __ldg((const uint4*)(muh + s * 32 + sub * 8));
    uint4 ub = __ldg((const uint4*)(muh + d * 32 + sub * 8));
    float p = 0.f;
    {
        float2 fa, fb;
        fa = __half22float2(*(__half2*)&ua.x); fb = __half22float2(*(__half2*)&ub.x);
        p += fa.x * fb.x + fa.y * fb.y;
        fa = __half22float2(*(__half2*)&ua.y); fb = __half22float2(*(__half2*)&ub.y);
        p += fa.x * fb.x + fa.y * fb.y;
        fa = __half22float2(*(__half2*)&ua.z); fb = __half22float2(*(__half2*)&ub.z);
        p += fa.x * fb.x + fa.y * fb.y;
        fa = __half22float2(*(__half2*)&ua.w); fb = __half22float2(*(__half2*)&ub.w);
        p += fa.x * fb.x + fa.y * fb.y;
    }
    p += __shfl_down_sync(~0u, p, 2);
    p += __shfl_down_sync(~0u, p, 1);
    if (sub == 0) probs[e] = 1.f / (1.f + expf(-p));
}

// ---------------- launch ----------------
extern "C" void kernel_launch(void* const* d_in, const int* in_sizes, int n_in,
                              void* d_out, int out_size) {
    const float* x   = (const float*)d_in[0];
    const int* ei    = (const int*)d_in[1];
    const int* src   = ei;
    const int* dst   = ei + EE;
    const float* Wm1 = (const float*)d_in[2];
    const float* bm1 = (const float*)d_in[3];
    const float* gm1 = (const float*)d_in[4];
    const float* hm1 = (const float*)d_in[5];
    const float* Wm2 = (const float*)d_in[6];
    const float* bm2 = (const float*)d_in[7];
    const float* gm2 = (const float*)d_in[8];
    const float* hm2 = (const float*)d_in[9];
    const float* Wm3 = (const float*)d_in[10];
    const float* bm3 = (const float*)d_in[11];
    const float* Wl1 = (const float*)d_in[12];
    const float* bl1 = (const float*)d_in[13];
    const float* gl1 = (const float*)d_in[14];
    const float* hl1 = (const float*)d_in[15];
    const float* Wl2 = (const float*)d_in[16];
    const float* bl2 = (const float*)d_in[17];
    const float* gl2 = (const float*)d_in[18];
    const float* hl2 = (const float*)d_in[19];
    const float* Wl3 = (const float*)d_in[20];
    const float* bl3 = (const float*)d_in[21];

    float* out = (float*)d_out;
    float* out_probs = out;
    float* out_mu = out + EE;
    float* out_ls = out + EE + NN * 32;

    __half *y0h, *axh, *raw1h, *y1h, *agg1h, *raw2h, *y3h, *muh;
    cudaGetSymbolAddress((void**)&y0h, g_y0h);
    cudaGetSymbolAddress((void**)&axh, g_axh);
    cudaGetSymbolAddress((void**)&raw1h, g_raw1h);
    cudaGetSymbolAddress((void**)&y1h, g_y1h);
    cudaGetSymbolAddress((void**)&agg1h, g_agg1h);
    cudaGetSymbolAddress((void**)&raw2h, g_raw2h);
    cudaGetSymbolAddress((void**)&y3h, g_y3h);
    cudaGetSymbolAddress((void**)&muh, g_muh);

    const int SM1 = 128 * 72 * 2 + 64 * 136 * 2;                       // 35,840
    const int SM2 = 64 * 136 * 2 + 2 * 64 * 136 * 2;                   // 52,224
    const int SM3 = 128 * 264 * 2 + 2 * 128 * 40 * 2 + 512 * 4;        // 90,112
    cudaFuncSetAttribute(k_gemm1, cudaFuncAttributeMaxDynamicSharedMemorySize, SM1);
    cudaFuncSetAttribute(k_gemm2, cudaFuncAttributeMaxDynamicSharedMemorySize, SM2);
    cudaFuncSetAttribute(k_gemm3, cudaFuncAttributeMaxDynamicSharedMemorySize, SM3);

    // degree + CSR (+ fused dinv/y0; state re-zeroed by later kernels each call)
    k_indeg<<<3125, 256>>>(dst);
    k_scan1<<<831, 1024>>>(x);
    k_scan3<<<49, 1024>>>();
    k_scatter<<<3125, 256>>>(src, dst);

    // layer 1
    k_agg1h<<<6250, 256>>>(y0h, axh);
    k_gemm1<<<391, 256, SM1>>>(axh, Wm1, Wl1, bm1, bl1, raw1h);
    k_stats1<<<391, 256>>>();
    k_ew1<<<6250, 256>>>(gm1, hm1, gl1, hl1);

    // layer 2
    k_agg2h<<<6250, 256>>>(y1h, agg1h);
    k_gemm2<<<782, 256, SM2>>>(agg1h, Wm2, Wl2, bm2, bl2, raw2h);
    k_stats2<<<391, 256>>>();

    // layer 3
    k_gemm3<<<391, 256, SM3>>>(raw2h, Wm3, Wl3, y3h, gm2, hm2, gl2, hl2);
    k_agg3f<<<6250, 256>>>(y3h, out_mu, bm3, bl3, out_ls);

    // decoder
    k_dec<<<12500, 256>>>(src, dst, muh, out_probs);
}

// round 16
// speedup vs baseline: 1.0598x; 1.0192x over previous
#include <cuda_runtime.h>
#include <cuda_fp16.h>
#include <cstdint>

#define NN 50000
#define EE 800000

typedef unsigned long long ull;
typedef unsigned int u32;

__device__ __forceinline__ u32 saddr(const void* p) {
    return (u32)__cvta_generic_to_shared(p);
}
__device__ __forceinline__ void ldsm_x4(u32 &a0, u32 &a1, u32 &a2, u32 &a3, u32 addr) {
    asm volatile("ldmatrix.sync.aligned.m8n8.x4.shared.b16 {%0,%1,%2,%3}, [%4];"
                 : "=r"(a0), "=r"(a1), "=r"(a2), "=r"(a3) : "r"(addr));
}
__device__ __forceinline__ void ldsm_x2t(u32 &b0, u32 &b1, u32 addr) {
    asm volatile("ldmatrix.sync.aligned.m8n8.x2.trans.shared.b16 {%0,%1}, [%2];"
                 : "=r"(b0), "=r"(b1) : "r"(addr));
}
__device__ __forceinline__ void mma16816(float &c0, float &c1, float &c2, float &c3,
                                         u32 a0, u32 a1, u32 a2, u32 a3,
                                         u32 b0, u32 b1) {
    asm volatile(
        "mma.sync.aligned.m16n8k16.row.col.f32.f16.f16.f32 "
        "{%0,%1,%2,%3}, {%4,%5,%6,%7}, {%8,%9}, {%0,%1,%2,%3};"
        : "+f"(c0), "+f"(c1), "+f"(c2), "+f"(c3)
        : "r"(a0), "r"(a1), "r"(a2), "r"(a3), "r"(b0), "r"(b1));
}

// ---------------- scratch ----------------
__device__ float g_dinv[NN];
__device__ int   g_indeg[NN];
__device__ int   g_off[NN + 1];
__device__ int   g_adj[EE];
__device__ int   g_rank[EE];
__device__ int   g_bsum[64];

__device__ __half g_y0h[NN * 64];
__device__ __half g_axh[NN * 64];
__device__ __half g_raw1h[NN * 128];
__device__ __half g_y1h[NN * 128];
__device__ __half g_agg1h[NN * 128];
__device__ __half g_raw2h[NN * 256];
__device__ __half g_y3h[NN * 64];
__device__ __half g_muh[NN * 32];

__device__ float g_ssum[512];
__device__ float g_ssq[512];

// ---------------- degree + per-edge rank ----------------
// g_indeg is zero on entry: zero-initialized at load, re-zeroed by k_agg1h each call.
__global__ void k_indeg(const int* __restrict__ dst) {
    int e = blockIdx.x * blockDim.x + threadIdx.x;
    if (e < EE) g_rank[e] = atomicAdd(&g_indeg[dst[e]], 1);
}

// ---------------- fused scan + dinv/y0 ----------------
__global__ void k_scan1(const float* __restrict__ x) {
    int bid = blockIdx.x;
    if (bid < 49) {
        int i = bid * 1024 + threadIdx.x;
        int v = (i < NN) ? g_indeg[i] : 0;
        int lane = threadIdx.x & 31, wid = threadIdx.x >> 5;
        int s = v;
        #pragma unroll
        for (int o = 1; o < 32; o <<= 1) {
            int t = __shfl_up_sync(~0u, s, o);
            if (lane >= o) s += t;
        }
        __shared__ int wsum[32];
        if (lane == 31) wsum[wid] = s;
        __syncthreads();
        if (wid == 0) {
            int ws = wsum[lane];
            #pragma unroll
            for (int o = 1; o < 32; o <<= 1) {
                int t = __shfl_up_sync(~0u, ws, o);
                if (lane >= o) ws += t;
            }
            wsum[lane] = ws;
        }
        __syncthreads();
        int incl = s + (wid > 0 ? wsum[wid - 1] : 0);
        if (i < NN) g_off[i + 1] = incl;
        if (threadIdx.x == 1023) g_bsum[bid] = incl;
    } else {
        int idx = (bid - 49) * 1024 + threadIdx.x;
        if (idx < NN * 16) {
            int row = idx >> 4;
            float d = rsqrtf((float)(g_indeg[row] + 1));
            if ((idx & 15) == 0) g_dinv[row] = d;
            float4 v = ((const float4*)x)[idx];
            __half2 h0 = __floats2half2_rn(v.x * d, v.y * d);
            __half2 h1 = __floats2half2_rn(v.z * d, v.w * d);
            ((uint2*)g_y0h)[idx] = make_uint2(*(unsigned*)&h0, *(unsigned*)&h1);
        }
    }
}

__global__ void k_scan3() {
    __shared__ int base;
    if (threadIdx.x == 0) {
        int acc = 0;
        for (int b = 0; b < blockIdx.x; b++) acc += g_bsum[b];
        base = acc;
    }
    __syncthreads();
    int i = blockIdx.x * 1024 + threadIdx.x;
    if (i < NN) g_off[i + 1] += base;
    if (i == 0) g_off[0] = 0;
}

// atomic-free scatter: position = off[dst] + precomputed rank
__global__ void k_scatter(const int* __restrict__ src, const int* __restrict__ dst) {
    int e = blockIdx.x * blockDim.x + threadIdx.x;
    if (e < EE) {
        int d = dst[e];
        g_adj[g_off[d] + g_rank[e]] = src[e];
    }
}

// ---------------- aggregations (proven) ----------------
// also re-zeroes g_indeg for the next call (last read was dinv in k_scan1)
__global__ void k_agg1h(const __half* __restrict__ y, __half* __restrict__ out) {
    int tid = blockIdx.x * blockDim.x + threadIdx.x;
    if (tid < NN) g_indeg[tid] = 0;
    int gw = tid >> 5;
    if (gw >= NN) return;
    int lane = threadIdx.x & 31;
    int beg = g_off[gw], end = g_off[gw + 1];
    float2 acc = __half22float2(*(const __half2*)(y + gw * 64 + lane * 2));
    for (int j = beg; j < end; j++) {
        int s = g_adj[j];
        float2 v = __half22float2(__ldg((const __half2*)(y + s * 64 + lane * 2)));
        acc.x += v.x; acc.y += v.y;
    }
    float d = g_dinv[gw];
    *(__half2*)(out + gw * 64 + lane * 2) = __floats2half2_rn(acc.x * d, acc.y * d);
}

// also re-zeroes g_ssum/g_ssq[0:128]
__global__ void k_agg2h(const __half* __restrict__ y, __half* __restrict__ out) {
    int tid = blockIdx.x * blockDim.x + threadIdx.x;
    if (tid < 128) { g_ssum[tid] = 0.f; g_ssq[tid] = 0.f; }
    int gw = tid >> 5;
    if (gw >= NN) return;
    int lane = threadIdx.x & 31;
    int beg = g_off[gw], end = g_off[gw + 1];
    uint2 u0 = *(const uint2*)(y + (size_t)gw * 128 + lane * 4);
    float2 a01 = __half22float2(*(__half2*)&u0.x);
    float2 a23 = __half22float2(*(__half2*)&u0.y);
    float4 acc = make_float4(a01.x, a01.y, a23.x, a23.y);
    for (int j = beg; j < end; j++) {
        int s = g_adj[j];
        uint2 u = __ldg((const uint2*)(y + (size_t)s * 128 + lane * 4));
        float2 f01 = __half22float2(*(__half2*)&u.x);
        float2 f23 = __half22float2(*(__half2*)&u.y);
        acc.x += f01.x; acc.y += f01.y; acc.z += f23.x; acc.w += f23.y;
    }
    float d = g_dinv[gw];
    __half2 h0 = __floats2half2_rn(acc.x * d, acc.y * d);
    __half2 h1 = __floats2half2_rn(acc.z * d, acc.w * d);
    *(uint2*)(out + (size_t)gw * 128 + lane * 4) = make_uint2(*(unsigned*)&h0, *(unsigned*)&h1);
}

// also re-zeroes g_ssum/g_ssq[256:512]
__global__ void k_agg3f(const __half* __restrict__ y, float* __restrict__ out_mu,
                        const float* __restrict__ bm3, const float* __restrict__ bl3,
                        float* __restrict__ out_ls) {
    int tid = blockIdx.x * blockDim.x + threadIdx.x;
    if (tid < 256) { g_ssum[256 + tid] = 0.f; g_ssq[256 + tid] = 0.f; }
    int gw = tid >> 5;
    if (gw >= NN) return;
    int lane = threadIdx.x & 31;
    int beg = g_off[gw], end = g_off[gw + 1];
    float2 acc = __half22float2(*(const __half2*)(y + gw * 64 + lane * 2));
    for (int j = beg; j < end; j++) {
        int s = g_adj[j];
        float2 v = __half22float2(__ldg((const __half2*)(y + s * 64 + lane * 2)));
        acc.x += v.x; acc.y += v.y;
    }
    float d = g_dinv[gw];
    acc.x *= d; acc.y *= d;
    int c = lane * 2;
    if (c < 32) {
        float m0 = acc.x + bm3[c];
        float m1 = acc.y + bm3[c + 1];
        out_mu[gw * 32 + c]     = m0;
        out_mu[gw * 32 + c + 1] = m1;
        *(__half2*)(g_muh + gw * 32 + c) = __floats2half2_rn(m0, m1);
    } else {
        out_ls[gw * 32 + c - 32] = fminf(acc.x + bl3[c - 32], 10.0f);
        out_ls[gw * 32 + c - 31] = fminf(acc.y + bl3[c - 31], 10.0f);
    }
}

// ---------------- layer-1 GEMM: HMMA (proven) ----------------
__global__ void __launch_bounds__(256) k_gemm1(
        const __half* __restrict__ A, const float* __restrict__ W1,
        const float* __restrict__ W2, const float* __restrict__ b1,
        const float* __restrict__ b2, __half* __restrict__ C) {
    extern __shared__ __align__(16) char smem1[];
    __half* Ah = (__half*)smem1;                      // [128][72]
    __half* Wh = (__half*)(smem1 + 128 * 72 * 2);     // [64][136]
    int tid = threadIdx.x;
    int row0 = blockIdx.x * 128;

    for (int i = tid; i < 4096; i += 256) {
        int k = i >> 6, n2 = i & 63;
        int n = n2 * 2;
        float2 wv = (n < 64) ? *(const float2*)(W1 + k * 64 + n)
                             : *(const float2*)(W2 + k * 64 + (n - 64));
        *(__half2*)(Wh + k * 136 + n) = __floats2half2_rn(wv.x, wv.y);
    }
    for (int i = tid; i < 2048; i += 256) {
        int r = i >> 4, q = i & 15;
        uint2 v = make_uint2(0u, 0u);
        if (row0 + r < NN) v = ((const uint2*)(A + (size_t)(row0 + r) * 64))[q];
        *(uint2*)(Ah + r * 72 + q * 4) = v;
    }
    __syncthreads();

    int warp = tid >> 5, lane = tid & 31;
    int R = warp * 16;
    float c[16][4];
    #pragma unroll
    for (int n0 = 0; n0 < 16; n0++)
        #pragma unroll
        for (int j = 0; j < 4; j++) c[n0][j] = 0.f;

    #pragma unroll
    for (int kc = 0; kc < 4; kc++) {
        u32 a0, a1, a2, a3;
        ldsm_x4(a0, a1, a2, a3,
                saddr(Ah + (R + (lane & 15)) * 72 + kc * 16 + (lane >> 4) * 8));
        #pragma unroll
        for (int n0 = 0; n0 < 16; n0++) {
            u32 b0, b1v;
            ldsm_x2t(b0, b1v, saddr(Wh + (kc * 16 + (lane & 15)) * 136 + n0 * 8));
            mma16816(c[n0][0], c[n0][1], c[n0][2], c[n0][3], a0, a1, a2, a3, b0, b1v);
        }
    }

    int rq = lane >> 2, cq = (lane & 3) * 2;
    int r0 = row0 + R + rq, r1 = r0 + 8;
    #pragma unroll
    for (int n0 = 0; n0 < 16; n0++) {
        int col = n0 * 8 + cq;
        float bb0 = (col < 64) ? b1[col] : b2[col - 64];
        float bb1 = (col < 64) ? b1[col + 1] : b2[col + 1 - 64];
        if (r0 < NN)
            *(__half2*)(C + (size_t)r0 * 128 + col) =
                __floats2half2_rn(c[n0][0] + bb0, c[n0][1] + bb1);
        if (r1 < NN)
            *(__half2*)(C + (size_t)r1 * 128 + col) =
                __floats2half2_rn(c[n0][2] + bb0, c[n0][3] + bb1);
    }
}

// ---------------- BN stats pass 1 ----------------
__global__ void __launch_bounds__(256) k_stats1() {
    __shared__ float red[256];
    int tid = threadIdx.x;
    int g = tid & 15, rsub = tid >> 4;
    int c0 = g * 8;
    bool rl = (c0 >= 64);
    int row0 = blockIdx.x * 128;
    float s[8], q[8];
    #pragma unroll
    for (int i = 0; i < 8; i++) { s[i] = 0.f; q[i] = 0.f; }
    for (int r = row0 + rsub; r < row0 + 128 && r < NN; r += 16) {
        uint4 u = *(const uint4*)(g_raw1h + (size_t)r * 128 + c0);
        u32 w[4] = {u.x, u.y, u.z, u.w};
        #pragma unroll
        for (int p = 0; p < 4; p++) {
            float2 f = __half22float2(*(__half2*)&w[p]);
            float v0 = rl ? fmaxf(f.x, 0.f) : f.x;
            float v1 = rl ? fmaxf(f.y, 0.f) : f.y;
            s[p * 2] += v0; q[p * 2] += v0 * v0;
            s[p * 2 + 1] += v1; q[p * 2 + 1] += v1 * v1;
        }
    }
    red[tid] = 0.f;
    __syncthreads();
    #pragma unroll
    for (int i = 0; i < 8; i++) {
        atomicAdd(&red[c0 + i], s[i]);
        atomicAdd(&red[128 + c0 + i], q[i]);
    }
    __syncthreads();
    if (tid < 128) {
        atomicAdd(&g_ssum[tid], red[tid]);
        atomicAdd(&g_ssq[tid], red[tid + 128]);
    }
}

// ---------------- BN stats pass 2 ----------------
__global__ void __launch_bounds__(256) k_stats2() {
    __shared__ float red[512];
    int tid = threadIdx.x;
    int g = tid & 31, rsub = tid >> 5;
    int c0 = g * 8;
    bool rl = (c0 >= 128);
    int row0 = blockIdx.x * 128;
    float s[8], q[8];
    #pragma unroll
    for (int i = 0; i < 8; i++) { s[i] = 0.f; q[i] = 0.f; }
    for (int r = row0 + rsub; r < row0 + 128 && r < NN; r += 8) {
        uint4 u = *(const uint4*)(g_raw2h + (size_t)r * 256 + c0);
        u32 w[4] = {u.x, u.y, u.z, u.w};
        #pragma unroll
        for (int p = 0; p < 4; p++) {
            float2 f = __half22float2(*(__half2*)&w[p]);
            float v0 = rl ? fmaxf(f.x, 0.f) : f.x;
            float v1 = rl ? fmaxf(f.y, 0.f) : f.y;
            s[p * 2] += v0; q[p * 2] += v0 * v0;
            s[p * 2 + 1] += v1; q[p * 2 + 1] += v1 * v1;
        }
    }
    red[tid] = 0.f; red[tid + 256] = 0.f;
    __syncthreads();
    #pragma unroll
    for (int i = 0; i < 8; i++) {
        atomicAdd(&red[c0 + i], s[i]);
        atomicAdd(&red[256 + c0 + i], q[i]);
    }
    __syncthreads();
    atomicAdd(&g_ssum[256 + tid], red[tid]);
    atomicAdd(&g_ssq[256 + tid], red[tid + 256]);
}

// elementwise layer1
__global__ void k_ew1(const float* __restrict__ g1, const float* __restrict__ h1,
                      const float* __restrict__ g2, const float* __restrict__ h2) {
    __shared__ float sa[128], sb[128];
    int tid = threadIdx.x;
    if (tid < 128) {
        float m = g_ssum[tid] * (1.0f / NN);
        float v = g_ssq[tid] * (1.0f / NN) - m * m;
        float rstd = rsqrtf(v + 1e-5f);
        float gamma = (tid < 64) ? g1[tid] : g2[tid - 64];
        float beta  = (tid < 64) ? h1[tid] : h2[tid - 64];
        float a = gamma * rstd;
        sa[tid] = a;
        sb[tid] = beta - m * a;
    }
    __syncthreads();
    int idx = blockIdx.x * blockDim.x + tid;
    if (idx >= NN * 32) return;
    int r = idx >> 5;
    int c4 = (idx & 31) << 2;
    uint2 u = ((const uint2*)g_raw1h)[idx];
    float2 v01 = __half22float2(*(__half2*)&u.x);
    float2 v23 = __half22float2(*(__half2*)&u.y);
    float d = g_dinv[r];
    float o[4]; float vv[4] = {v01.x, v01.y, v23.x, v23.y};
    #pragma unroll
    for (int t = 0; t < 4; t++) {
        int c = c4 + t;
        float a = sa[c], b = sb[c];
        if (c4 < 64) o[t] = fmaxf(vv[t] * a + b, 0.f);
        else         o[t] = fmaxf(vv[t], 0.f) * a + b;
        o[t] *= d;
    }
    __half2 h0 = __floats2half2_rn(o[0], o[1]);
    __half2 h1v = __floats2half2_rn(o[2], o[3]);
    ((uint2*)g_y1h)[idx] = make_uint2(*(unsigned*)&h0, *(unsigned*)&h1v);
}

// ---------------- layer-2 GEMM: HMMA (proven) ----------------
__global__ void __launch_bounds__(256) k_gemm2(
        const __half* __restrict__ A, const float* __restrict__ W1,
        const float* __restrict__ W2, const float* __restrict__ b1,
        const float* __restrict__ b2, __half* __restrict__ C) {
    extern __shared__ __align__(16) char smem2[];
    __half* Ah = (__half*)smem2;                       // [64][136]
    __half* Wh = (__half*)(smem2 + 64 * 136 * 2);      // [2][64][136]
    int tid = threadIdx.x;
    int row0 = blockIdx.x * 64;

    for (int i = tid; i < 8192; i += 256) {
        int h = i >> 12, j = i & 4095;
        int k = j >> 6, n2 = j & 63;
        int n = n2 * 2;
        const float* W = h ? W2 : W1;
        float2 wv = *(const float2*)(W + k * 128 + n);
        *(__half2*)(Wh + h * 64 * 136 + k * 136 + n) = __floats2half2_rn(wv.x, wv.y);
    }
    for (int i = tid; i < 2048; i += 256) {
        int r = i >> 5, q = i & 31;
        uint2 v = make_uint2(0u, 0u);
        if (row0 + r < NN) v = ((const uint2*)(A + (size_t)(row0 + r) * 128))[q];
        *(uint2*)(Ah + r * 136 + q * 4) = v;
    }
    __syncthreads();

    int warp = tid >> 5, lane = tid & 31;
    int h = warp >> 2;
    int R = (warp & 3) * 16;
    float c[16][4];
    #pragma unroll
    for (int n0 = 0; n0 < 16; n0++)
        #pragma unroll
        for (int j = 0; j < 4; j++) c[n0][j] = 0.f;

    #pragma unroll
    for (int kc = 0; kc < 4; kc++) {
        u32 a0, a1, a2, a3;
        ldsm_x4(a0, a1, a2, a3,
                saddr(Ah + (R + (lane & 15)) * 136 + h * 64 + kc * 16 + (lane >> 4) * 8));
        #pragma unroll
        for (int n0 = 0; n0 < 16; n0++) {
            u32 b0, b1v;
            ldsm_x2t(b0, b1v,
                     saddr(Wh + h * 64 * 136 + (kc * 16 + (lane & 15)) * 136 + n0 * 8));
            mma16816(c[n0][0], c[n0][1], c[n0][2], c[n0][3], a0, a1, a2, a3, b0, b1v);
        }
    }

    int rq = lane >> 2, cq = (lane & 3) * 2;
    int r0 = row0 + R + rq, r1 = r0 + 8;
    const float* bp = h ? b2 : b1;
    #pragma unroll
    for (int n0 = 0; n0 < 16; n0++) {
        int cl = n0 * 8 + cq;
        int cg = h * 128 + cl;
        float bb0 = bp[cl], bb1 = bp[cl + 1];
        if (r0 < NN)
            *(__half2*)(C + (size_t)r0 * 256 + cg) =
                __floats2half2_rn(c[n0][0] + bb0, c[n0][1] + bb1);
        if (r1 < NN)
            *(__half2*)(C + (size_t)r1 * 256 + cg) =
                __floats2half2_rn(c[n0][2] + bb0, c[n0][3] + bb1);
    }
}

// ---------------- layer-3 GEMM: HMMA, BN-on-load, statfin folded (proven) ----------------
__global__ void __launch_bounds__(256) k_gemm3(
        const __half* __restrict__ raw2, const float* __restrict__ Wm3,
        const float* __restrict__ Wl3, __half* __restrict__ y3,
        const float* __restrict__ g1, const float* __restrict__ h1,
        const float* __restrict__ g2, const float* __restrict__ h2) {
    extern __shared__ __align__(16) char smem3[];
    __half* Ah = (__half*)smem3;                        // [128][264]
    __half* Wh = (__half*)(smem3 + 128 * 264 * 2);      // [2][128][40]
    float* sa = (float*)(smem3 + 128 * 264 * 2 + 2 * 128 * 40 * 2);  // [256]
    float* sb = sa + 256;                                              // [256]
    int tid = threadIdx.x;
    int row0 = blockIdx.x * 128;

    {
        float m = g_ssum[256 + tid] * (1.0f / NN);
        float v = g_ssq[256 + tid] * (1.0f / NN) - m * m;
        float rstd = rsqrtf(v + 1e-5f);
        float gamma = (tid < 128) ? g1[tid] : g2[tid - 128];
        float beta  = (tid < 128) ? h1[tid] : h2[tid - 128];
        float a = gamma * rstd;
        sa[tid] = a;
        sb[tid] = beta - m * a;
    }

    for (int i = tid; i < 4096; i += 256) {
        int h = i >> 11, j = i & 2047;
        int k = j >> 4, n2 = j & 15;
        int n = n2 * 2;
        const float* W = h ? Wl3 : Wm3;
        float2 wv = *(const float2*)(W + k * 32 + n);
        *(__half2*)(Wh + h * 128 * 40 + k * 40 + n) = __floats2half2_rn(wv.x, wv.y);
    }
    __syncthreads();

    for (int i = tid; i < 8192; i += 256) {
        int r = i >> 6, q = i & 63;
        int c4 = q * 4;
        int half = (c4 >= 128) ? 1 : 0;
        uint2 u = make_uint2(0u, 0u);
        if (row0 + r < NN)
            u = ((const uint2*)(raw2 + (size_t)(row0 + r) * 256))[q];
        float2 p01 = __half22float2(*(__half2*)&u.x);
        float2 p23 = __half22float2(*(__half2*)&u.y);
        float vv[4] = {p01.x, p01.y, p23.x, p23.y};
        float o[4];
        #pragma unroll
        for (int t = 0; t < 4; t++) {
            int col = c4 + t;
            float a = sa[col], b = sb[col];
            if (half == 0) o[t] = fmaxf(vv[t] * a + b, 0.f);
            else           o[t] = fmaxf(vv[t], 0.f) * a + b;
        }
        __half2 ha = __floats2half2_rn(o[0], o[1]);
        __half2 hb = __floats2half2_rn(o[2], o[3]);
        *(uint2*)(Ah + r * 264 + c4) = make_uint2(*(unsigned*)&ha, *(unsigned*)&hb);
    }
    __syncthreads();

    int warp = tid >> 5, lane = tid & 31;
    int h = warp >> 2;
    int R = (warp & 3) * 32;
    float c[2][4][4];
    #pragma unroll
    for (int m = 0; m < 2; m++)
        #pragma unroll
        for (int n0 = 0; n0 < 4; n0++)
            #pragma unroll
            for (int j = 0; j < 4; j++) c[m][n0][j] = 0.f;

    #pragma unroll
    for (int kc = 0; kc < 8; kc++) {
        u32 b0[4], b1v[4];
        #pragma unroll
        for (int n0 = 0; n0 < 4; n0++)
            ldsm_x2t(b0[n0], b1v[n0],
                     saddr(Wh + h * 128 * 40 + (kc * 16 + (lane & 15)) * 40 + n0 * 8));
        #pragma unroll
        for (int m = 0; m < 2; m++) {
            u32 a0, a1, a2, a3;
            ldsm_x4(a0, a1, a2, a3,
                    saddr(Ah + (R + m * 16 + (lane & 15)) * 264 + h * 128 + kc * 16 + (lane >> 4) * 8));
            #pragma unroll
            for (int n0 = 0; n0 < 4; n0++)
                mma16816(c[m][n0][0], c[m][n0][1], c[m][n0][2], c[m][n0][3],
                         a0, a1, a2, a3, b0[n0], b1v[n0]);
        }
    }

    int rq = lane >> 2, cq = (lane & 3) * 2;
    #pragma unroll
    for (int m = 0; m < 2; m++) {
        int r0 = row0 + R + m * 16 + rq, r1 = r0 + 8;
        #pragma unroll
        for (int n0 = 0; n0 < 4; n0++) {
            int col = h * 32 + n0 * 8 + cq;
            if (r0 < NN) {
                float d = g_dinv[r0];
                *(__half2*)(y3 + (size_t)r0 * 64 + col) =
                    __floats2half2_rn(c[m][n0][0] * d, c[m][n0][1] * d);
            }
            if (r1 < NN) {
                float d = g_dinv[r1];
                *(__half2*)(y3 + (size_t)r1 * 64 + col) =
                    __floats2half2_rn(c[m][n0][2] * d, c[m][n0][3] * d);
            }
        }
    }
}

// ---------------- decoder ----------------
__global__ void k_dec(const int* __restrict__ src, const int* __restrict__ dst,
                      const __half* __restrict__ muh, float* __restrict__ probs) {
    int t = blockIdx.x * blockDim.x + threadIdx.x;
    int e = t >> 2, sub = t & 3;
    int s = src[e], d = dst[e];
    uint4 ua = __ldg((const uint4*)(muh + s * 32 + sub * 8));
    uint4 ub = __ldg((const uint4*)(muh + d * 32 + sub * 8));
    float p = 0.f;
    {
        float2 fa, fb;
        fa = __half22float2(*(__half2*)&ua.x); fb = __half22float2(*(__half2*)&ub.x);
        p += fa.x * fb.x + fa.y * fb.y;
        fa = __half22float2(*(__half2*)&ua.y); fb = __half22float2(*(__half2*)&ub.y);
        p += fa.x * fb.x + fa.y * fb.y;
        fa = __half22float2(*(__half2*)&ua.z); fb = __half22float2(*(__half2*)&ub.z);
        p += fa.x * fb.x + fa.y * fb.y;
        fa = __half22float2(*(__half2*)&ua.w); fb = __half22float2(*(__half2*)&ub.w);
        p += fa.x * fb.x + fa.y * fb.y;
    }
    p += __shfl_down_sync(~0u, p, 2);
    p += __shfl_down_sync(~0u, p, 1);
    if (sub == 0) probs[e] = 1.f / (1.f + expf(-p));
}

// ---------------- launch ----------------
extern "C" void kernel_launch(void* const* d_in, const int* in_sizes, int n_in,
                              void* d_out, int out_size) {
    const float* x   = (const float*)d_in[0];
    const int* ei    = (const int*)d_in[1];
    const int* src   = ei;
    const int* dst   = ei + EE;
    const float* Wm1 = (const float*)d_in[2];
    const float* bm1 = (const float*)d_in[3];
    const float* gm1 = (const float*)d_in[4];
    const float* hm1 = (const float*)d_in[5];
    const float* Wm2 = (const float*)d_in[6];
    const float* bm2 = (const float*)d_in[7];
    const float* gm2 = (const float*)d_in[8];
    const float* hm2 = (const float*)d_in[9];
    const float* Wm3 = (const float*)d_in[10];
    const float* bm3 = (const float*)d_in[11];
    const float* Wl1 = (const float*)d_in[12];
    const float* bl1 = (const float*)d_in[13];
    const float* gl1 = (const float*)d_in[14];
    const float* hl1 = (const float*)d_in[15];
    const float* Wl2 = (const float*)d_in[16];
    const float* bl2 = (const float*)d_in[17];
    const float* gl2 = (const float*)d_in[18];
    const float* hl2 = (const float*)d_in[19];
    const float* Wl3 = (const float*)d_in[20];
    const float* bl3 = (const float*)d_in[21];

    float* out = (float*)d_out;
    float* out_probs = out;
    float* out_mu = out + EE;
    float* out_ls = out + EE + NN * 32;

    __half *y0h, *axh, *raw1h, *y1h, *agg1h, *raw2h, *y3h, *muh;
    cudaGetSymbolAddress((void**)&y0h, g_y0h);
    cudaGetSymbolAddress((void**)&axh, g_axh);
    cudaGetSymbolAddress((void**)&raw1h, g_raw1h);
    cudaGetSymbolAddress((void**)&y1h, g_y1h);
    cudaGetSymbolAddress((void**)&agg1h, g_agg1h);
    cudaGetSymbolAddress((void**)&raw2h, g_raw2h);
    cudaGetSymbolAddress((void**)&y3h, g_y3h);
    cudaGetSymbolAddress((void**)&muh, g_muh);

    const int SM1 = 128 * 72 * 2 + 64 * 136 * 2;                       // 35,840
    const int SM2 = 64 * 136 * 2 + 2 * 64 * 136 * 2;                   // 52,224
    const int SM3 = 128 * 264 * 2 + 2 * 128 * 40 * 2 + 512 * 4;        // 90,112
    cudaFuncSetAttribute(k_gemm1, cudaFuncAttributeMaxDynamicSharedMemorySize, SM1);
    cudaFuncSetAttribute(k_gemm2, cudaFuncAttributeMaxDynamicSharedMemorySize, SM2);
    cudaFuncSetAttribute(k_gemm3, cudaFuncAttributeMaxDynamicSharedMemorySize, SM3);

    // degree (+rank) + CSR (+ fused dinv/y0)
    k_indeg<<<3125, 256>>>(dst);
    k_scan1<<<831, 1024>>>(x);
    k_scan3<<<49, 1024>>>();
    k_scatter<<<3125, 256>>>(src, dst);

    // layer 1
    k_agg1h<<<6250, 256>>>(y0h, axh);
    k_gemm1<<<391, 256, SM1>>>(axh, Wm1, Wl1, bm1, bl1, raw1h);
    k_stats1<<<391, 256>>>();
    k_ew1<<<6250, 256>>>(gm1, hm1, gl1, hl1);

    // layer 2
    k_agg2h<<<6250, 256>>>(y1h, agg1h);
    k_gemm2<<<782, 256, SM2>>>(agg1h, Wm2, Wl2, bm2, bl2, raw2h);
    k_stats2<<<391, 256>>>();

    // layer 3
    k_gemm3<<<391, 256, SM3>>>(raw2h, Wm3, Wl3, y3h, gm2, hm2, gl2, hl2);
    k_agg3f<<<6250, 256>>>(y3h, out_mu, bm3, bl3, out_ls);

    // decoder
    k_dec<<<12500, 256>>>(src, dst, muh, out_probs);
}